// round 13
// baseline (speedup 1.0000x reference)
#include <cuda_runtime.h>

// OWA pooling: 3x3 / stride 2 / pad(0,1,0,1) over (16,224,224,64) f32 NHWC.
// Per output element: descending-sort the 9 window values, dot with kernel[:,c].
//
// R10: block-level smem input tiling. Each block = 16x4 output pixels x 4
// channel-chunks (16 ch). Cooperative load of the 33x9-pixel input tile into
// shared memory (~4.6 LDG.128/thread, once), then 9 conflict-free LDS.128 per
// thread feed the packed-f32x2 sort (R7 compute, best instr economy).
// Smem layout: per-chunk blocks (stride 298 u16B -> 8-bank shift), rows of 33,
// even/odd column split so stride-2 window reads are unit-stride.

namespace {

constexpr int H_IN = 224, W_IN = 224;
constexpr int H_OUT = 112, W_OUT = 112;
constexpr int C4 = 16;          // 16-byte chunks per pixel (64 ch / 4)
constexpr int BLOCK = 256;

constexpr int TW = 16, TH = 4;  // output tile 16x4 pixels
constexpr int CH = 4;           // chunks per block (16 channels)
constexpr int IN_W = 33, IN_H = 9;          // input tile pixels
constexpr int RS = 33;                      // smem row stride, 16B units
constexpr int CS = IN_H * RS + 1;           // 298: chunk stride (+1 pad -> 8-bank shift)
constexpr int NLOAD = IN_H * IN_W * CH;     // 1188 float4 loads per block

constexpr int TILES_X = W_OUT / TW;         // 7
constexpr int TILES_Y = H_OUT / TH;         // 28

constexpr unsigned long long NEG1X2 = 0xBF800000BF800000ULL;  // {-1.f, -1.f}

__device__ __forceinline__ void cash2(unsigned long long& A, unsigned long long& B) {
  asm("{\n\t"
      ".reg .f32 al, ah, bl, bh, hl, hh;\n\t"
      ".reg .b64 s64;\n\t"
      "add.rn.f32x2 s64, %0, %1;\n\t"
      "mov.b64 {al, ah}, %0;\n\t"
      "mov.b64 {bl, bh}, %1;\n\t"
      "max.f32 hl, al, bl;\n\t"
      "max.f32 hh, ah, bh;\n\t"
      "mov.b64 %1, {hl, hh};\n\t"
      "fma.rn.f32x2 %0, %1, %2, s64;\n\t"
      "}"
      : "+l"(A), "+l"(B)
      : "l"(NEG1X2));
}

__device__ __forceinline__ void fma2(unsigned long long& acc,
                                     unsigned long long v,
                                     unsigned long long w) {
  asm("fma.rn.f32x2 %0, %1, %2, %0;" : "+l"(acc) : "l"(v), "l"(w));
}

// Published optimal 9-element sorting network: 25 comparators, depth 7.
__device__ __forceinline__ void sort9p(unsigned long long (&a)[9],
                                       unsigned long long (&b)[9]) {
#define CE(i,j) cash2(a[i],a[j]); cash2(b[i],b[j]);
  CE(0,3) CE(1,7) CE(2,5) CE(4,8)
  CE(0,7) CE(2,4) CE(3,8) CE(5,6)
  CE(0,2) CE(1,3) CE(4,5) CE(7,8)
  CE(1,4) CE(3,6) CE(5,7)
  CE(0,1) CE(2,4) CE(3,5) CE(6,8)
  CE(2,3) CE(4,5) CE(6,7)
  CE(1,2) CE(3,4) CE(5,6)
#undef CE
}

} // namespace

__global__ __launch_bounds__(BLOCK, 4)
void owa_pool_kernel(const ulonglong2* __restrict__ in2,
                     const ulonglong2* __restrict__ wk2,
                     ulonglong2* __restrict__ out2) {
  __shared__ ulonglong2 sm[CH * CS];   // 4 * 298 * 16B = 19,072 B

  int bid = blockIdx.x;
  int tileX = bid % TILES_X;  int tmp = bid / TILES_X;
  int tileY = tmp % TILES_Y;  tmp /= TILES_Y;
  int c4g = tmp & 3;          int b = tmp >> 2;

  int x0 = tileX * (2 * TW);  // 32
  int y0 = tileY * (2 * TH);  // 8

  // ---- cooperative tile load (zero-fill OOB) ----
  for (int i = threadIdx.x; i < NLOAD; i += BLOCK) {
    int chunk = i & 3;
    int cc = i >> 2;          // 0..296
    int col = cc % IN_W;
    int row = cc / IN_W;
    int y = y0 + row, x = x0 + col;
    ulonglong2 val = make_ulonglong2(0ULL, 0ULL);
    if (y < H_IN && x < W_IN)
      val = __ldg(&in2[((b * H_IN + y) * W_IN + x) * C4 + c4g * 4 + chunk]);
    int colIdx = (col & 1) ? (17 + (col >> 1)) : (col >> 1);  // even/odd split
    sm[chunk * CS + row * RS + colIdx] = val;
  }
  __syncthreads();

  // ---- per-thread window from smem ----
  int tid = threadIdx.x;
  int cLoc = tid & 3;
  int px = (tid >> 2) & 15;
  int py = tid >> 6;

  const ulonglong2* smc = sm + cLoc * CS;

  unsigned long long vxy[9], vzw[9];
#pragma unroll
  for (int ky = 0; ky < 3; ++ky) {
    int r = (2 * py + ky) * RS;
    ulonglong2 t0 = smc[r + px];            // kx=0 (even col 2px)
    ulonglong2 t1 = smc[r + 17 + px];       // kx=1 (odd col 2px+1)
    ulonglong2 t2 = smc[r + px + 1];        // kx=2 (even col 2px+2)
    vxy[ky * 3 + 0] = t0.x;  vzw[ky * 3 + 0] = t0.y;
    vxy[ky * 3 + 1] = t1.x;  vzw[ky * 3 + 1] = t1.y;
    vxy[ky * 3 + 2] = t2.x;  vzw[ky * 3 + 2] = t2.y;
  }

  // Ascending sort; weight k applies to the k-th LARGEST -> pair v[i] with w[8-i].
  sort9p(vxy, vzw);

  int c4 = c4g * 4 + cLoc;
  unsigned long long axy = 0ULL, azw = 0ULL;
  const ulonglong2* wkc = wk2 + c4;
#pragma unroll
  for (int k = 0; k < 9; ++k) {
    ulonglong2 w = __ldg(wkc + (8 - k) * C4);
    fma2(axy, vxy[k], w.x);
    fma2(azw, vzw[k], w.y);
  }

  int ow = tileX * TW + px;
  int oh = tileY * TH + py;
  out2[((b * H_OUT + oh) * W_OUT + ow) * C4 + c4] = make_ulonglong2(axy, azw);
}

extern "C" void kernel_launch(void* const* d_in, const int* in_sizes, int n_in,
                              void* d_out, int out_size) {
  const ulonglong2* in2 = (const ulonglong2*)d_in[0];   // (16,224,224,64) f32
  const ulonglong2* wk2 = (const ulonglong2*)d_in[1];   // (9,64) f32
  ulonglong2* out2 = (ulonglong2*)d_out;                // (16,112,112,64) f32

  (void)in_sizes; (void)n_in; (void)out_size;
  int grid = TILES_X * TILES_Y * 4 * 16;                // 12544
  owa_pool_kernel<<<grid, BLOCK>>>(in2, wk2, out2);
}

// round 14
// speedup vs baseline: 1.6568x; 1.6568x over previous
#include <cuda_runtime.h>

// OWA pooling: 3x3 / stride 2 / pad(0,1,0,1) over (16,224,224,64) f32 NHWC.
// Per output element: descending-sort the 9 window values, dot with kernel[:,c].
//
// R11: batch-strided multi-pixel loop. One thread = (2 channels, one (oh,ow))
// x 8 batch images (b = b0 + 2p). Index math, border predicates, and the 9
// weights (preloaded, reversed) amortized over 8 pixels; per iteration only
// 9 LDG.64 + packed-f32x2 sort (100 instr) + 9 FFMA2 + STG + 2 pointer bumps.
//
// Compare-exchange (packed, hybrid):
//   s  = add.rn.f32x2(A, B)        (fma pipe)
//   hi = {max(al,bl), max(ah,bh)}  (2x FMNMX, alu pipe; exact)
//   A  = fma.rn.f32x2(hi, -1, s)   (fma pipe)  => lo, <=1 ulp-of-sum error

namespace {

constexpr int H_IN = 224, W_IN = 224;
constexpr int H_OUT = 112, W_OUT = 112;
constexpr int C2 = 32;                        // u64 (2-channel) chunks per pixel
constexpr int BLOCK = 128;
constexpr int NPIX = 8;                       // pixels per thread (batch-strided)
constexpr int B_SPLIT = 2;                    // b0 in {0,1}
constexpr int TOTALT = H_OUT * W_OUT * C2 * B_SPLIT;   // 802,816 threads

constexpr int IN_ROW = W_IN * C2;             // 7168 u64 per input row
constexpr int IN_IMG = H_IN * IN_ROW;         // per image
constexpr int OUT_IMG = H_OUT * W_OUT * C2;
constexpr int IN_STRIDE = B_SPLIT * IN_IMG;   // loop stride (2 images)
constexpr int OUT_STRIDE = B_SPLIT * OUT_IMG;

constexpr unsigned long long NEG1X2 = 0xBF800000BF800000ULL;  // {-1.f, -1.f}

__device__ __forceinline__ void cash2(unsigned long long& A, unsigned long long& B) {
  asm("{\n\t"
      ".reg .f32 al, ah, bl, bh, hl, hh;\n\t"
      ".reg .b64 s64;\n\t"
      "add.rn.f32x2 s64, %0, %1;\n\t"
      "mov.b64 {al, ah}, %0;\n\t"
      "mov.b64 {bl, bh}, %1;\n\t"
      "max.f32 hl, al, bl;\n\t"
      "max.f32 hh, ah, bh;\n\t"
      "mov.b64 %1, {hl, hh};\n\t"
      "fma.rn.f32x2 %0, %1, %2, s64;\n\t"
      "}"
      : "+l"(A), "+l"(B)
      : "l"(NEG1X2));
}

__device__ __forceinline__ void fma2(unsigned long long& acc,
                                     unsigned long long v,
                                     unsigned long long w) {
  asm("fma.rn.f32x2 %0, %1, %2, %0;" : "+l"(acc) : "l"(v), "l"(w));
}

// Published optimal 9-element sorting network: 25 comparators, depth 7.
__device__ __forceinline__ void sort9p(unsigned long long (&v)[9]) {
  cash2(v[0],v[3]); cash2(v[1],v[7]); cash2(v[2],v[5]); cash2(v[4],v[8]);
  cash2(v[0],v[7]); cash2(v[2],v[4]); cash2(v[3],v[8]); cash2(v[5],v[6]);
  cash2(v[0],v[2]); cash2(v[1],v[3]); cash2(v[4],v[5]); cash2(v[7],v[8]);
  cash2(v[1],v[4]); cash2(v[3],v[6]); cash2(v[5],v[7]);
  cash2(v[0],v[1]); cash2(v[2],v[4]); cash2(v[3],v[5]); cash2(v[6],v[8]);
  cash2(v[2],v[3]); cash2(v[4],v[5]); cash2(v[6],v[7]);
  cash2(v[1],v[2]); cash2(v[3],v[4]); cash2(v[5],v[6]);
}

} // namespace

__global__ __launch_bounds__(BLOCK, 9)
void owa_pool_kernel(const unsigned long long* __restrict__ in2,
                     const unsigned long long* __restrict__ wk2,
                     unsigned long long* __restrict__ out2) {
  int tid = blockIdx.x * BLOCK + threadIdx.x;

  int c2 = tid & (C2 - 1);
  int r  = tid >> 5;
  int ow = r % W_OUT;
  int r2 = r / W_OUT;
  int oh = r2 % H_OUT;
  int b0 = r2 / H_OUT;            // 0 or 1

  int y0 = oh * 2, x0 = ow * 2;
  bool pY = (y0 + 2) < H_IN;      // bottom row in bounds?
  bool pX = (x0 + 2) < W_IN;      // right col in bounds?

  // Preload reversed weights: wreg[k] pairs with ascending-sorted v[k].
  unsigned long long wreg[9];
#pragma unroll
  for (int k = 0; k < 9; ++k)
    wreg[k] = __ldg(&wk2[(8 - k) * C2 + c2]);

  int inOff  = (b0 * H_IN + y0) * IN_ROW + x0 * C2 + c2;
  int outOff = (b0 * H_OUT + oh) * W_OUT * C2 + ow * C2 + c2;

#pragma unroll 1
  for (int p = 0; p < NPIX; ++p) {
    const unsigned long long* w0 = in2 + inOff;

    unsigned long long v[9];
    // rows ky=0,1 always valid; ky=2 gated by pY; kx=2 gated by pX.
    v[0] = __ldg(w0);
    v[1] = __ldg(w0 + C2);
    v[2] = pX ? __ldg(w0 + 2 * C2) : 0ULL;
    v[3] = __ldg(w0 + IN_ROW);
    v[4] = __ldg(w0 + IN_ROW + C2);
    v[5] = pX ? __ldg(w0 + IN_ROW + 2 * C2) : 0ULL;
    v[6] = pY ? __ldg(w0 + 2 * IN_ROW) : 0ULL;
    v[7] = pY ? __ldg(w0 + 2 * IN_ROW + C2) : 0ULL;
    v[8] = (pY && pX) ? __ldg(w0 + 2 * IN_ROW + 2 * C2) : 0ULL;

    sort9p(v);

    unsigned long long acc = 0ULL;  // {0.f, 0.f}
#pragma unroll
    for (int k = 0; k < 9; ++k) fma2(acc, v[k], wreg[k]);

    out2[outOff] = acc;

    inOff  += IN_STRIDE;
    outOff += OUT_STRIDE;
  }
}

extern "C" void kernel_launch(void* const* d_in, const int* in_sizes, int n_in,
                              void* d_out, int out_size) {
  const unsigned long long* in2 = (const unsigned long long*)d_in[0];  // (16,224,224,64) f32
  const unsigned long long* wk2 = (const unsigned long long*)d_in[1];  // (9,64) f32
  unsigned long long* out2 = (unsigned long long*)d_out;               // (16,112,112,64) f32

  (void)in_sizes; (void)n_in; (void)out_size;
  int grid = TOTALT / BLOCK;   // 6272
  owa_pool_kernel<<<grid, BLOCK>>>(in2, wk2, out2);
}

// round 15
// speedup vs baseline: 1.9247x; 1.1617x over previous
#include <cuda_runtime.h>

// OWA pooling: 3x3 / stride 2 / pad(0,1,0,1) over (16,224,224,64) f32 NHWC.
// Per output element: descending-sort the 9 window values, dot with kernel[:,c].
//
// R12: R11's amortized batch-strided loop + R7's dual-chain ILP.
// One thread = 2 channels x 8 batch-strided pixels, processed 2 pixels per
// iteration as TWO independent packed-f32x2 sort chains (18 batched loads,
// interleaved comparators). Weights preloaded once (reversed); per iteration
// only pointer bumps as bookkeeping.
//
// Compare-exchange (packed, hybrid):
//   s  = add.rn.f32x2(A, B)        (fma pipe)
//   hi = {max(al,bl), max(ah,bh)}  (2x FMNMX, alu pipe; exact)
//   A  = fma.rn.f32x2(hi, -1, s)   (fma pipe)  => lo, <=1 ulp-of-sum error

namespace {

constexpr int H_IN = 224, W_IN = 224;
constexpr int H_OUT = 112, W_OUT = 112;
constexpr int C2 = 32;                        // u64 (2-channel) chunks per pixel
constexpr int BLOCK = 128;
constexpr int B_SPLIT = 2;                    // b0 in {0,1}
constexpr int NPAIR = 4;                      // 4 iterations x 2 pixels = 8
constexpr int TOTALT = H_OUT * W_OUT * C2 * B_SPLIT;   // 802,816 threads

constexpr int IN_ROW = W_IN * C2;             // 7168 u64 per input row
constexpr int IN_IMG = H_IN * IN_ROW;
constexpr int OUT_IMG = H_OUT * W_OUT * C2;
constexpr int IN_STRIDE = B_SPLIT * IN_IMG;   // stride between consecutive pixels (2 images)
constexpr int OUT_STRIDE = B_SPLIT * OUT_IMG;

constexpr unsigned long long NEG1X2 = 0xBF800000BF800000ULL;  // {-1.f, -1.f}

__device__ __forceinline__ void cash2(unsigned long long& A, unsigned long long& B) {
  asm("{\n\t"
      ".reg .f32 al, ah, bl, bh, hl, hh;\n\t"
      ".reg .b64 s64;\n\t"
      "add.rn.f32x2 s64, %0, %1;\n\t"
      "mov.b64 {al, ah}, %0;\n\t"
      "mov.b64 {bl, bh}, %1;\n\t"
      "max.f32 hl, al, bl;\n\t"
      "max.f32 hh, ah, bh;\n\t"
      "mov.b64 %1, {hl, hh};\n\t"
      "fma.rn.f32x2 %0, %1, %2, s64;\n\t"
      "}"
      : "+l"(A), "+l"(B)
      : "l"(NEG1X2));
}

__device__ __forceinline__ void fma2(unsigned long long& acc,
                                     unsigned long long v,
                                     unsigned long long w) {
  asm("fma.rn.f32x2 %0, %1, %2, %0;" : "+l"(acc) : "l"(v), "l"(w));
}

// Published optimal 9-element sorting network: 25 comparators, depth 7.
// Two independent chains interleaved for ILP.
__device__ __forceinline__ void sort9p2(unsigned long long (&a)[9],
                                        unsigned long long (&b)[9]) {
#define CE(i,j) cash2(a[i],a[j]); cash2(b[i],b[j]);
  CE(0,3) CE(1,7) CE(2,5) CE(4,8)
  CE(0,7) CE(2,4) CE(3,8) CE(5,6)
  CE(0,2) CE(1,3) CE(4,5) CE(7,8)
  CE(1,4) CE(3,6) CE(5,7)
  CE(0,1) CE(2,4) CE(3,5) CE(6,8)
  CE(2,3) CE(4,5) CE(6,7)
  CE(1,2) CE(3,4) CE(5,6)
#undef CE
}

} // namespace

__global__ __launch_bounds__(BLOCK, 8)
void owa_pool_kernel(const unsigned long long* __restrict__ in2,
                     const unsigned long long* __restrict__ wk2,
                     unsigned long long* __restrict__ out2) {
  int tid = blockIdx.x * BLOCK + threadIdx.x;

  int c2 = tid & (C2 - 1);
  int r  = tid >> 5;
  int ow = r % W_OUT;
  int r2 = r / W_OUT;
  int oh = r2 % H_OUT;
  int b0 = r2 / H_OUT;            // 0 or 1

  int y0 = oh * 2, x0 = ow * 2;
  bool pY = (y0 + 2) < H_IN;      // bottom row in bounds?
  bool pX = (x0 + 2) < W_IN;      // right col in bounds?

  // Preload reversed weights: wreg[k] pairs with ascending-sorted v[k].
  unsigned long long wreg[9];
#pragma unroll
  for (int k = 0; k < 9; ++k)
    wreg[k] = __ldg(&wk2[(8 - k) * C2 + c2]);

  int inOff  = (b0 * H_IN + y0) * IN_ROW + x0 * C2 + c2;
  int outOff = (b0 * H_OUT + oh) * W_OUT * C2 + ow * C2 + c2;

#pragma unroll 1
  for (int p = 0; p < NPAIR; ++p) {
    const unsigned long long* wa = in2 + inOff;
    const unsigned long long* wb = wa + IN_STRIDE;

    // Batch all 18 loads (2 pixels) for MLP before either sort begins.
    unsigned long long va[9], vb[9];
    va[0] = __ldg(wa);
    va[1] = __ldg(wa + C2);
    va[2] = pX ? __ldg(wa + 2 * C2) : 0ULL;
    va[3] = __ldg(wa + IN_ROW);
    va[4] = __ldg(wa + IN_ROW + C2);
    va[5] = pX ? __ldg(wa + IN_ROW + 2 * C2) : 0ULL;
    va[6] = pY ? __ldg(wa + 2 * IN_ROW) : 0ULL;
    va[7] = pY ? __ldg(wa + 2 * IN_ROW + C2) : 0ULL;
    va[8] = (pY && pX) ? __ldg(wa + 2 * IN_ROW + 2 * C2) : 0ULL;

    vb[0] = __ldg(wb);
    vb[1] = __ldg(wb + C2);
    vb[2] = pX ? __ldg(wb + 2 * C2) : 0ULL;
    vb[3] = __ldg(wb + IN_ROW);
    vb[4] = __ldg(wb + IN_ROW + C2);
    vb[5] = pX ? __ldg(wb + IN_ROW + 2 * C2) : 0ULL;
    vb[6] = pY ? __ldg(wb + 2 * IN_ROW) : 0ULL;
    vb[7] = pY ? __ldg(wb + 2 * IN_ROW + C2) : 0ULL;
    vb[8] = (pY && pX) ? __ldg(wb + 2 * IN_ROW + 2 * C2) : 0ULL;

    sort9p2(va, vb);

    unsigned long long accA = 0ULL, accB = 0ULL;  // {0.f, 0.f}
#pragma unroll
    for (int k = 0; k < 9; ++k) {
      fma2(accA, va[k], wreg[k]);
      fma2(accB, vb[k], wreg[k]);
    }

    out2[outOff] = accA;
    out2[outOff + OUT_STRIDE] = accB;

    inOff  += 2 * IN_STRIDE;
    outOff += 2 * OUT_STRIDE;
  }
}

extern "C" void kernel_launch(void* const* d_in, const int* in_sizes, int n_in,
                              void* d_out, int out_size) {
  const unsigned long long* in2 = (const unsigned long long*)d_in[0];  // (16,224,224,64) f32
  const unsigned long long* wk2 = (const unsigned long long*)d_in[1];  // (9,64) f32
  unsigned long long* out2 = (unsigned long long*)d_out;               // (16,112,112,64) f32

  (void)in_sizes; (void)n_in; (void)out_size;
  int grid = TOTALT / BLOCK;   // 6272
  owa_pool_kernel<<<grid, BLOCK>>>(in2, wk2, out2);
}